// round 10
// baseline (speedup 1.0000x reference)
#include <cuda_runtime.h>
#include <cuda_bf16.h>
#include <mma.h>
#include <cstdint>

using namespace nvcuda;

// ---------------- problem constants ----------------
#define Bv    8
#define P0v   20000
#define P1v   5000
#define P2v   1250
#define Mv    10
#define Wv    9
#define C0v   3
#define C1v   64
#define C2v   128
#define K2v   576            // W*C1
#define NROW  (Bv*P1v)       // 40000 GEMM rows
#define KDv   (P2v*C2v)      // 160000
#define LOUT  512            // 2*LATENT
#define KSPLIT 25
#define KCHUNK (KDv/KSPLIT)  // 6400

// ---------------- device scratch ----------------
__device__ __align__(128) float g_h0[Bv*(size_t)P0v*C1v];
__device__ __align__(128) float g_h1[Bv*(size_t)P1v*C1v];
__device__ __align__(128) float g_h2[Bv*(size_t)P1v*C2v];
__device__ __align__(128) float g_h3[Bv*(size_t)P2v*C2v];
__device__ __align__(128) __nv_bfloat16 g_Shi[(size_t)NROW*K2v];
__device__ __align__(128) __nv_bfloat16 g_Slo[(size_t)NROW*K2v];
__device__ __align__(128) __nv_bfloat16 g_Whi[K2v*C2v];
__device__ __align__(128) __nv_bfloat16 g_Wlo[K2v*C2v];
__device__ __align__(128) float g_part[KSPLIT*Bv*LOUT];

__device__ __forceinline__ float elu(float x) {
    return x > 0.f ? x : expm1f(x);
}
__device__ __forceinline__ uint32_t smem_to_u32(const void* p) {
    uint32_t a;
    asm("{ .reg .u64 tmp; cvta.to.shared.u64 tmp, %1; cvt.u32.u64 %0, tmp; }"
        : "=r"(a) : "l"(p));
    return a;
}
__device__ __forceinline__ void cp_async16(uint32_t d, const void* s, int srcsize) {
    asm volatile("cp.async.ca.shared.global [%0], [%1], 16, %2;"
                 :: "r"(d), "l"(s), "r"(srcsize) : "memory");
}

// ================= kernel 1: conv0 + ELU (8 points per block) ======
#define CPTS 8
__global__ void __launch_bounds__(512) conv0_kernel(
    const float* __restrict__ x, const int* __restrict__ nb0,
    const float* __restrict__ w0, const float* __restrict__ bias0,
    const float* __restrict__ ww0)
{
    __shared__ float Wt[27][C1v];
    __shared__ float wws[CPTS][Mv*Wv];
    __shared__ int   nbs[CPTS][Mv];
    __shared__ float xg[CPTS][Bv][32];
    __shared__ float s[CPTS][Bv][28];

    const int p0 = blockIdx.x * CPTS;
    const int t  = threadIdx.x;

    for (int e = t; e < 27*C1v; e += 512) {
        int k = e >> 6, o = e & 63;
        Wt[k][o] = w0[(k/3)*192 + o*3 + (k%3)];
    }
    if (t < CPTS*Mv) nbs[t/Mv][t%Mv] = nb0[p0*Mv + t];
    for (int e = t; e < CPTS*Mv*Wv; e += 512)
        wws[e/(Mv*Wv)][e%(Mv*Wv)] = ww0[p0*Mv*Wv + e];
    __syncthreads();

    for (int e = t; e < CPTS*Bv*Mv*C0v; e += 512) {
        int j = e / 240, r = e % 240;
        int b = r / 30, q = r % 30;
        int m = q / 3, i = q % 3;
        int idx = nbs[j][m];
        xg[j][b][q] = (idx < P0v) ? x[((size_t)b*P0v + idx)*C0v + i] : 0.f;
    }
    __syncthreads();

    for (int e = t; e < CPTS*Bv*27; e += 512) {
        int j = e / 216, r = e % 216;
        int b = r / 27, k = r % 27;
        int w = k / 3, i = k % 3;
        float acc = 0.f;
        #pragma unroll
        for (int m = 0; m < Mv; m++) acc += wws[j][m*Wv + w] * xg[j][b][m*3 + i];
        s[j][b][k] = acc;
    }
    __syncthreads();

    const int tx = t & 63, ty = t >> 6;
    const float bia = bias0[tx];
    #pragma unroll
    for (int j = 0; j < CPTS; j++) {
        float acc = bia;
        #pragma unroll
        for (int k = 0; k < 27; k++) acc += s[j][ty][k] * Wt[k][tx];
        g_h0[((size_t)ty*P0v + p0 + j)*C1v + tx] = elu(acc);
    }
}

// ================= pooling (pool1 / pool3) + ELU ===================
template<int C, int Pin, int Pout, int STAGE>
__global__ void pool_kernel(const int* __restrict__ nb,
                            const float* __restrict__ pnb)
{
    const float* __restrict__ hin  = (STAGE == 0) ? g_h0 : g_h2;
    float*       __restrict__ hout = (STAGE == 0) ? g_h1 : g_h3;

    __shared__ int   nbs[Mv];
    __shared__ float wt[Mv];
    const int p = blockIdx.x;
    const int t = threadIdx.x;
    if (t < Mv) {
        int idx = nb[p*Mv + t];
        nbs[t] = idx;
        wt[t]  = (idx < Pin) ? fabsf(pnb[p*Mv + t]) : 0.f;
    }
    __syncthreads();
    float denom = 1e-8f;
    #pragma unroll
    for (int m = 0; m < Mv; m++) denom += wt[m];

    const int c = t % C, b = t / C;
    float acc = 0.f;
    #pragma unroll
    for (int m = 0; m < Mv; m++) {
        int idx = nbs[m];
        if (idx < Pin) acc += wt[m] * hin[((size_t)b*Pin + idx)*C + c];
    }
    acc /= denom;
    hout[((size_t)b*Pout + p)*C + c] = elu(acc);
}

// ====== conv2 stage A: S -> bf16 hi/lo planes; + fused weight split ====
__global__ void __launch_bounds__(512) conv2s_kernel(
    const int* __restrict__ nb2, const float* __restrict__ ww2,
    const float* __restrict__ w2)
{
    if (blockIdx.x < 144) {
        int e = blockIdx.x * 512 + threadIdx.x;
        int k = e >> 7, n = e & 127;
        float v = w2[(k >> 6)*(C2v*C1v) + n*C1v + (k & 63)];
        __nv_bfloat16 hi = __float2bfloat16(v);
        g_Whi[e] = hi;
        g_Wlo[e] = __float2bfloat16(v - __bfloat162float(hi));
    }

    __shared__ int   nbs[Mv];
    __shared__ float wws[Mv*Wv];
    const int p = blockIdx.x;
    const int t = threadIdx.x;
    if (t < Mv)    nbs[t] = nb2[p*Mv + t];
    if (t < Mv*Wv) wws[t] = ww2[p*Mv*Wv + t];
    __syncthreads();

    const int i = t & 63, b = t >> 6;
    float acc[Wv];
    #pragma unroll
    for (int w = 0; w < Wv; w++) acc[w] = 0.f;
    #pragma unroll
    for (int m = 0; m < Mv; m++) {
        int idx = nbs[m];
        if (idx < P1v) {
            float v = g_h1[((size_t)b*P1v + idx)*C1v + i];
            #pragma unroll
            for (int w = 0; w < Wv; w++) acc[w] += wws[m*Wv + w] * v;
        }
    }
    const size_t r = (size_t)b*P1v + p;
    #pragma unroll
    for (int w = 0; w < Wv; w++) {
        size_t idx = (r*Wv + w)*C1v + i;
        __nv_bfloat16 hi = __float2bfloat16(acc[w]);
        g_Shi[idx] = hi;
        g_Slo[idx] = __float2bfloat16(acc[w] - __bfloat162float(hi));
    }
}

// ================= wmma bf16x3 GEMM: h2 = ELU(S @ W + bias2) =======
// CTA 128x128, 128 thr (4 warps 2x2, warp tile 64x64), k-step 32,
// 2-stage cp.async double buffer, one __syncthreads per k-step.
// MMA:frag-load ratio = 3 (ILP-driven latency hiding, CUTLASS shape).
#define GKS    32
#define GNST   (K2v/GKS)        // 18
#define A_LD   40
#define B_LD   136
#define A_PLe  (128*A_LD)       // 5120 elems per plane
#define B_PLe  (GKS*B_LD)       // 4352 elems per plane
#define STGe   (2*A_PLe + 2*B_PLe)   // 18944 elems
#define STGb   (2*STGe)              // 37888 bytes per stage
#define EPI_LD 132
#define GEMM_SMEM (2*STGb)           // 75776 (epilogue needs 67584)

__global__ void __launch_bounds__(128) gemm_wmma_kernel(const float* __restrict__ bias2)
{
    extern __shared__ char sm[];
    __nv_bfloat16* smb = (__nv_bfloat16*)sm;
    const uint32_t sb = smem_to_u32(sm);
    const int t = threadIdx.x;
    const int warp = t >> 5;
    const int wm = warp & 1, wn = warp >> 1;    // 2 x 2, warp tile 64x64
    const int m0 = blockIdx.x * 128;

    // A loader: thread t owns row t, 4 k-segments of 8 bf16 (16B)
    const int g_arow = m0 + t;
    const int a_sz  = (g_arow < NROW) ? 16 : 0;
    const int a_cl  = (g_arow < NROW) ? g_arow : 0;

    wmma::fragment<wmma::accumulator, 16, 16, 16, float> acc[4][4];
    #pragma unroll
    for (int i = 0; i < 4; i++)
        #pragma unroll
        for (int j = 0; j < 4; j++) wmma::fill_fragment(acc[i][j], 0.f);

    auto stage_load = [&](int c, int s) {
        const int k0 = c * GKS;
        const uint32_t sa = sb + (uint32_t)s * STGb;
        const size_t aoff = (size_t)a_cl * K2v + k0;
        #pragma unroll
        for (int seg = 0; seg < 4; seg++) {
            cp_async16(sa + (uint32_t)(t*A_LD + seg*8)*2,         g_Shi + aoff + seg*8, a_sz);
            cp_async16(sa + (uint32_t)(A_PLe + t*A_LD + seg*8)*2, g_Slo + aoff + seg*8, a_sz);
        }
        #pragma unroll
        for (int j = 0; j < 4; j++) {
            const int idx = t*4 + j;           // 0..511
            const int kr = idx >> 4, ns = (idx & 15) * 8;
            const size_t boff = (size_t)(k0 + kr) * C2v + ns;
            cp_async16(sa + (uint32_t)(2*A_PLe + kr*B_LD + ns)*2,         g_Whi + boff, 16);
            cp_async16(sa + (uint32_t)(2*A_PLe + B_PLe + kr*B_LD + ns)*2, g_Wlo + boff, 16);
        }
        asm volatile("cp.async.commit_group;" ::: "memory");
    };

    stage_load(0, 0);

    for (int c = 0; c < GNST; c++) {
        const int s = c & 1;
        asm volatile("cp.async.wait_group 0;" ::: "memory");
        __syncthreads();
        if (c + 1 < GNST) stage_load(c + 1, s ^ 1);

        const __nv_bfloat16* stg = smb + (size_t)s * STGe;
        #pragma unroll
        for (int kk = 0; kk < 2; kk++) {
            wmma::fragment<wmma::matrix_a, 16, 16, 16, __nv_bfloat16, wmma::row_major> fah[4], fal[4];
            #pragma unroll
            for (int i = 0; i < 4; i++) {
                const __nv_bfloat16* p = stg + (size_t)(wm*64 + i*16)*A_LD + kk*16;
                wmma::load_matrix_sync(fah[i], p, A_LD);
                wmma::load_matrix_sync(fal[i], p + A_PLe, A_LD);
            }
            wmma::fragment<wmma::matrix_b, 16, 16, 16, __nv_bfloat16, wmma::row_major> fbh[4], fbl[4];
            #pragma unroll
            for (int j = 0; j < 4; j++) {
                const __nv_bfloat16* p = stg + 2*A_PLe + (size_t)(kk*16)*B_LD + wn*64 + j*16;
                wmma::load_matrix_sync(fbh[j], p, B_LD);
                wmma::load_matrix_sync(fbl[j], p + B_PLe, B_LD);
            }
            #pragma unroll
            for (int i = 0; i < 4; i++)
                #pragma unroll
                for (int j = 0; j < 4; j++) {
                    wmma::mma_sync(acc[i][j], fah[i], fbh[j], acc[i][j]);
                    wmma::mma_sync(acc[i][j], fal[i], fbh[j], acc[i][j]);
                    wmma::mma_sync(acc[i][j], fah[i], fbl[j], acc[i][j]);
                }
        }
    }
    __syncthreads();   // protect smem reuse (epilogue overlaps stage buffers)

    // epilogue: accum -> smem fp32 -> bias + ELU -> coalesced store
    float* et = (float*)sm;
    #pragma unroll
    for (int i = 0; i < 4; i++)
        #pragma unroll
        for (int j = 0; j < 4; j++)
            wmma::store_matrix_sync(et + (size_t)(wm*64 + i*16)*EPI_LD + wn*64 + j*16,
                                    acc[i][j], EPI_LD, wmma::mem_row_major);
    __syncthreads();

    // 128 threads: each owns one row (128 cols = 32 float4)
    if (m0 + t < NROW) {
        #pragma unroll
        for (int cf = 0; cf < 32; cf++) {
            float4 v = *(const float4*)(et + (size_t)t*EPI_LD + cf*4);
            float4 o;
            o.x = elu(v.x + __ldg(&bias2[cf*4 + 0]));
            o.y = elu(v.y + __ldg(&bias2[cf*4 + 1]));
            o.z = elu(v.z + __ldg(&bias2[cf*4 + 2]));
            o.w = elu(v.w + __ldg(&bias2[cf*4 + 3]));
            *(float4*)(g_h2 + (size_t)(m0 + t)*C2v + cf*4) = o;
        }
    }
}

// ================= final dense (HBM streaming, float4) =============
__global__ void __launch_bounds__(256) dense_kernel(
    const float* __restrict__ Wm, const float* __restrict__ Ws)
{
    const int warp = threadIdx.x >> 5, lane = threadIdx.x & 31;
    const int l0 = blockIdx.x * 32 + warp * 4;
    const int ks = blockIdx.y;
    const int k0 = ks * KCHUNK;

    const float* Wp = (l0 < 256) ? (Wm + (size_t)l0 * KDv)
                                 : (Ws + (size_t)(l0 - 256) * KDv);
    const float* f = g_h3;

    float acc[4][8];
    #pragma unroll
    for (int j = 0; j < 4; j++)
        #pragma unroll
        for (int b = 0; b < 8; b++) acc[j][b] = 0.f;

    for (int k = k0 + lane*4; k < k0 + KCHUNK; k += 128) {
        float4 fv[8];
        #pragma unroll
        for (int b = 0; b < 8; b++) fv[b] = *(const float4*)(f + (size_t)b*KDv + k);
        #pragma unroll
        for (int j = 0; j < 4; j++) {
            float4 wv = *(const float4*)(Wp + (size_t)j*KDv + k);
            #pragma unroll
            for (int b = 0; b < 8; b++) {
                acc[j][b] += wv.x * fv[b].x + wv.y * fv[b].y
                           + wv.z * fv[b].z + wv.w * fv[b].w;
            }
        }
    }

    #pragma unroll
    for (int j = 0; j < 4; j++)
        #pragma unroll
        for (int b = 0; b < 8; b++) {
            float v = acc[j][b];
            #pragma unroll
            for (int off = 16; off > 0; off >>= 1)
                v += __shfl_xor_sync(0xffffffffu, v, off);
            acc[j][b] = v;
        }

    if (lane == 0) {
        #pragma unroll
        for (int j = 0; j < 4; j++)
            #pragma unroll
            for (int b = 0; b < 8; b++)
                g_part[((size_t)ks*Bv + b)*LOUT + l0 + j] = acc[j][b];
    }
}

__global__ void reduce_kernel(const float* __restrict__ bm,
                              const float* __restrict__ bs,
                              float* __restrict__ out)
{
    int e = blockIdx.x * 256 + threadIdx.x;
    if (e >= Bv*LOUT) return;
    int b = e >> 9, l = e & 511;
    float acc = (l < 256) ? bm[l] : bs[l - 256];
    #pragma unroll 5
    for (int ks = 0; ks < KSPLIT; ks++)
        acc += g_part[((size_t)ks*Bv + b)*LOUT + l];
    out[e] = acc;
}

// ================= launch =========================================
extern "C" void kernel_launch(void* const* d_in, const int* in_sizes, int n_in,
                              void* d_out, int out_size)
{
    const float* x    = (const float*)d_in[0];
    const int*   nb0  = (const int*)  d_in[1];
    const int*   nb1  = (const int*)  d_in[2];
    const int*   nb2  = (const int*)  d_in[3];
    const int*   nb3  = (const int*)  d_in[4];
    const float* w0   = (const float*)d_in[5];
    const float* bia0 = (const float*)d_in[6];
    const float* ww0  = (const float*)d_in[7];
    const float* pn1  = (const float*)d_in[8];
    const float* w2   = (const float*)d_in[9];
    const float* bia2 = (const float*)d_in[10];
    const float* ww2  = (const float*)d_in[11];
    const float* pn3  = (const float*)d_in[12];
    const float* Wm   = (const float*)d_in[13];
    const float* bm   = (const float*)d_in[14];
    const float* Ws   = (const float*)d_in[15];
    const float* bs   = (const float*)d_in[16];
    float* out = (float*)d_out;

    cudaFuncSetAttribute(gemm_wmma_kernel,
                         cudaFuncAttributeMaxDynamicSharedMemorySize, GEMM_SMEM);

    conv0_kernel<<<P0v/CPTS, 512>>>(x, nb0, w0, bia0, ww0);
    pool_kernel<C1v, P0v, P1v, 0><<<P1v, C1v*Bv>>>(nb1, pn1);
    conv2s_kernel<<<P1v, 512>>>(nb2, ww2, w2);
    gemm_wmma_kernel<<<(NROW + 127)/128, 128, GEMM_SMEM>>>(bia2);
    pool_kernel<C2v, P1v, P2v, 1><<<P2v, C2v*Bv>>>(nb3, pn3);
    dense_kernel<<<dim3(16, KSPLIT), 256>>>(Wm, Ws);
    reduce_kernel<<<(Bv*LOUT + 255)/256, 256>>>(bm, bs, out);
}

// round 13
// speedup vs baseline: 1.1612x; 1.1612x over previous
#include <cuda_runtime.h>
#include <cuda_fp16.h>
#include <cuda_bf16.h>
#include <mma.h>
#include <cstdint>

using namespace nvcuda;

// ---------------- problem constants ----------------
#define Bv    8
#define P0v   20000
#define P1v   5000
#define P2v   1250
#define Mv    10
#define Wv    9
#define C0v   3
#define C1v   64
#define C2v   128
#define K2v   576            // W*C1
#define NROW  (Bv*P1v)       // 40000 GEMM rows
#define KDv   (P2v*C2v)      // 160000
#define LOUT  512            // 2*LATENT
#define KSPLIT 25
#define KCHUNK (KDv/KSPLIT)  // 6400

// ---------------- device scratch ----------------
__device__ __align__(128) float g_h0[Bv*(size_t)P0v*C1v];
__device__ __align__(128) float g_h1[Bv*(size_t)P1v*C1v];
__device__ __align__(128) float g_h2[Bv*(size_t)P1v*C2v];
__device__ __align__(128) float g_h3[Bv*(size_t)P2v*C2v];
__device__ __align__(128) __half g_Sh [(size_t)NROW*K2v];   // 46.08 MB (single fp16 plane)
__device__ __align__(128) __half g_Whi[K2v*C2v];
__device__ __align__(128) __half g_Wlo[K2v*C2v];
__device__ __align__(128) float g_part[KSPLIT*Bv*LOUT];

__device__ __forceinline__ float elu(float x) {
    return x > 0.f ? x : expm1f(x);
}
__device__ __forceinline__ uint32_t smem_to_u32(const void* p) {
    uint32_t a;
    asm("{ .reg .u64 tmp; cvta.to.shared.u64 tmp, %1; cvt.u32.u64 %0, tmp; }"
        : "=r"(a) : "l"(p));
    return a;
}
__device__ __forceinline__ void cp_async16(uint32_t d, const void* s, int srcsize) {
    asm volatile("cp.async.ca.shared.global [%0], [%1], 16, %2;"
                 :: "r"(d), "l"(s), "r"(srcsize) : "memory");
}

// ================= kernel 1: conv0 + ELU (8 points per block) ======
#define CPTS 8
__global__ void __launch_bounds__(512) conv0_kernel(
    const float* __restrict__ x, const int* __restrict__ nb0,
    const float* __restrict__ w0, const float* __restrict__ bias0,
    const float* __restrict__ ww0)
{
    __shared__ float Wt[27][C1v];
    __shared__ float wws[CPTS][Mv*Wv];
    __shared__ int   nbs[CPTS][Mv];
    __shared__ float xg[CPTS][Bv][32];
    __shared__ float s[CPTS][Bv][28];

    const int p0 = blockIdx.x * CPTS;
    const int t  = threadIdx.x;

    for (int e = t; e < 27*C1v; e += 512) {
        int k = e >> 6, o = e & 63;
        Wt[k][o] = w0[(k/3)*192 + o*3 + (k%3)];
    }
    if (t < CPTS*Mv) nbs[t/Mv][t%Mv] = nb0[p0*Mv + t];
    for (int e = t; e < CPTS*Mv*Wv; e += 512)
        wws[e/(Mv*Wv)][e%(Mv*Wv)] = ww0[p0*Mv*Wv + e];
    __syncthreads();

    for (int e = t; e < CPTS*Bv*Mv*C0v; e += 512) {
        int j = e / 240, r = e % 240;
        int b = r / 30, q = r % 30;
        int m = q / 3, i = q % 3;
        int idx = nbs[j][m];
        xg[j][b][q] = (idx < P0v) ? x[((size_t)b*P0v + idx)*C0v + i] : 0.f;
    }
    __syncthreads();

    for (int e = t; e < CPTS*Bv*27; e += 512) {
        int j = e / 216, r = e % 216;
        int b = r / 27, k = r % 27;
        int w = k / 3, i = k % 3;
        float acc = 0.f;
        #pragma unroll
        for (int m = 0; m < Mv; m++) acc += wws[j][m*Wv + w] * xg[j][b][m*3 + i];
        s[j][b][k] = acc;
    }
    __syncthreads();

    const int tx = t & 63, ty = t >> 6;
    const float bia = bias0[tx];
    #pragma unroll
    for (int j = 0; j < CPTS; j++) {
        float acc = bia;
        #pragma unroll
        for (int k = 0; k < 27; k++) acc += s[j][ty][k] * Wt[k][tx];
        g_h0[((size_t)ty*P0v + p0 + j)*C1v + tx] = elu(acc);
    }
}

// ================= pooling (pool1 / pool3) + ELU ===================
template<int C, int Pin, int Pout, int STAGE>
__global__ void pool_kernel(const int* __restrict__ nb,
                            const float* __restrict__ pnb)
{
    const float* __restrict__ hin  = (STAGE == 0) ? g_h0 : g_h2;
    float*       __restrict__ hout = (STAGE == 0) ? g_h1 : g_h3;

    __shared__ int   nbs[Mv];
    __shared__ float wt[Mv];
    const int p = blockIdx.x;
    const int t = threadIdx.x;
    if (t < Mv) {
        int idx = nb[p*Mv + t];
        nbs[t] = idx;
        wt[t]  = (idx < Pin) ? fabsf(pnb[p*Mv + t]) : 0.f;
    }
    __syncthreads();
    float denom = 1e-8f;
    #pragma unroll
    for (int m = 0; m < Mv; m++) denom += wt[m];

    const int c = t % C, b = t / C;
    float acc = 0.f;
    #pragma unroll
    for (int m = 0; m < Mv; m++) {
        int idx = nbs[m];
        if (idx < Pin) acc += wt[m] * hin[((size_t)b*Pin + idx)*C + c];
    }
    acc /= denom;
    hout[((size_t)b*Pout + p)*C + c] = elu(acc);
}

// ====== conv2 stage A: S -> single fp16 plane; + fused weight hi/lo split ====
// 256 threads: thread = (i0 = 2 channels, b); float2 gathers, half2 stores.
__global__ void __launch_bounds__(256) conv2s_kernel(
    const int* __restrict__ nb2, const float* __restrict__ ww2,
    const float* __restrict__ w2)
{
    // fused weight split: 144 blocks x 512 elems (2 per thread)
    if (blockIdx.x < 144) {
        #pragma unroll
        for (int r = 0; r < 2; r++) {
            int e = blockIdx.x * 512 + r * 256 + threadIdx.x;
            int k = e >> 7, n = e & 127;
            float v = w2[(k >> 6)*(C2v*C1v) + n*C1v + (k & 63)];
            __half hi = __float2half(v);
            g_Whi[e] = hi;
            g_Wlo[e] = __float2half(v - __half2float(hi));
        }
    }

    __shared__ int   nbs[Mv];
    __shared__ float wws[Mv*Wv];
    const int p = blockIdx.x;
    const int t = threadIdx.x;
    if (t < Mv)    nbs[t] = nb2[p*Mv + t];
    if (t < Mv*Wv) wws[t] = ww2[p*Mv*Wv + t];
    __syncthreads();

    const int i0 = (t & 31) * 2, b = t >> 5;
    float2 acc[Wv];
    #pragma unroll
    for (int w = 0; w < Wv; w++) acc[w] = make_float2(0.f, 0.f);
    #pragma unroll
    for (int m = 0; m < Mv; m++) {
        int idx = nbs[m];
        if (idx < P1v) {
            float2 v = *(const float2*)(g_h1 + ((size_t)b*P1v + idx)*C1v + i0);
            #pragma unroll
            for (int w = 0; w < Wv; w++) {
                float ww = wws[m*Wv + w];
                acc[w].x += ww * v.x;
                acc[w].y += ww * v.y;
            }
        }
    }
    const size_t r = (size_t)b*P1v + p;
    #pragma unroll
    for (int w = 0; w < Wv; w++) {
        *(__half2*)(g_Sh + (r*Wv + w)*C1v + i0) =
            __floats2half2_rn(acc[w].x, acc[w].y);
    }
}

// ================= wmma fp16 2-term GEMM: h2 = ELU(S @ W + bias2) ===
// CTA 128x128, 512 thr (warps 4x4, warp tile 32x32), k-step 32,
// 3-stage cp.async. A = single fp16 plane; B = fp16 hi+lo planes.
// acc += a*b_hi; acc += a*b_lo   (weights exact to 2^-22, activations fp16)
#define GKS    32
#define GNST   (K2v/GKS)        // 18
#define A_LD   40
#define B_LD   136
#define A_PLe  (128*A_LD)       // 5120 halves
#define B_PLe  (GKS*B_LD)       // 4352 halves
#define STGe   (A_PLe + 2*B_PLe)     // 13824 halves
#define STGb   (2*STGe)              // 27648 bytes per stage
#define NSTG   3
#define EPI_LD 132
#define GEMM_SMEM (NSTG*STGb)        // 82944 (epilogue needs 67584)

__global__ void __launch_bounds__(512) gemm_wmma_kernel(const float* __restrict__ bias2)
{
    extern __shared__ char sm[];
    __half* smh = (__half*)sm;
    const uint32_t sb = smem_to_u32(sm);
    const int t = threadIdx.x;
    const int warp = t >> 5;
    const int wm = warp & 3, wn = warp >> 2;    // 4 x 4
    const int m0 = blockIdx.x * 128;

    // A loader: a_row 0..127, 4 threads x 8 halves cover k=32
    const int a_row = t >> 2, a_ks = (t & 3) * 8;
    // B loader: 32 k-rows x 128 n
    const int b_kr  = t >> 4, b_ns = (t & 15) * 8;
    const int g_arow = m0 + a_row;
    const int a_sz  = (g_arow < NROW) ? 16 : 0;
    const int a_cl  = (g_arow < NROW) ? g_arow : 0;

    wmma::fragment<wmma::accumulator, 16, 16, 16, float> acc[2][2];
    #pragma unroll
    for (int i = 0; i < 2; i++)
        #pragma unroll
        for (int j = 0; j < 2; j++) wmma::fill_fragment(acc[i][j], 0.f);

    auto stage_load = [&](int c, int s) {
        const int k0 = c * GKS;
        const uint32_t sa = sb + (uint32_t)s * STGb;
        const size_t aoff = (size_t)a_cl * K2v + k0 + a_ks;
        cp_async16(sa + (uint32_t)(a_row*A_LD + a_ks)*2, g_Sh + aoff, a_sz);
        const size_t boff = (size_t)(k0 + b_kr) * C2v + b_ns;
        cp_async16(sa + (uint32_t)(A_PLe + b_kr*B_LD + b_ns)*2,         g_Whi + boff, 16);
        cp_async16(sa + (uint32_t)(A_PLe + B_PLe + b_kr*B_LD + b_ns)*2, g_Wlo + boff, 16);
        asm volatile("cp.async.commit_group;" ::: "memory");
    };

    stage_load(0, 0);
    stage_load(1, 1);

    for (int c = 0; c < GNST; c++) {
        const int s = c % NSTG;
        if (c + 1 < GNST) {
            asm volatile("cp.async.wait_group 1;" ::: "memory");
        } else {
            asm volatile("cp.async.wait_group 0;" ::: "memory");
        }
        __syncthreads();
        if (c + 2 < GNST) stage_load(c + 2, (c + 2) % NSTG);

        const __half* stg = smh + (size_t)s * STGe;
        #pragma unroll
        for (int kk = 0; kk < 2; kk++) {
            wmma::fragment<wmma::matrix_a, 16, 16, 16, __half, wmma::row_major> fa[2];
            #pragma unroll
            for (int i = 0; i < 2; i++) {
                const __half* p = stg + (size_t)(wm*32 + i*16)*A_LD + kk*16;
                wmma::load_matrix_sync(fa[i], p, A_LD);
            }
            wmma::fragment<wmma::matrix_b, 16, 16, 16, __half, wmma::row_major> fbh[2], fbl[2];
            #pragma unroll
            for (int j = 0; j < 2; j++) {
                const __half* p = stg + A_PLe + (size_t)(kk*16)*B_LD + wn*32 + j*16;
                wmma::load_matrix_sync(fbh[j], p, B_LD);
                wmma::load_matrix_sync(fbl[j], p + B_PLe, B_LD);
            }
            #pragma unroll
            for (int i = 0; i < 2; i++)
                #pragma unroll
                for (int j = 0; j < 2; j++) {
                    wmma::mma_sync(acc[i][j], fa[i], fbh[j], acc[i][j]);
                    wmma::mma_sync(acc[i][j], fa[i], fbl[j], acc[i][j]);
                }
        }
    }
    __syncthreads();   // protect smem reuse (epilogue overlaps stage buffers)

    // epilogue: accum -> smem fp32 -> bias + ELU -> coalesced store
    float* et = (float*)sm;
    #pragma unroll
    for (int i = 0; i < 2; i++)
        #pragma unroll
        for (int j = 0; j < 2; j++)
            wmma::store_matrix_sync(et + (size_t)(wm*32 + i*16)*EPI_LD + wn*32 + j*16,
                                    acc[i][j], EPI_LD, wmma::mem_row_major);
    __syncthreads();

    const int row = t >> 2, c0 = (t & 3) * 32;
    if (m0 + row < NROW) {
        #pragma unroll
        for (int cf = 0; cf < 8; cf++) {
            float4 v = *(const float4*)(et + (size_t)row*EPI_LD + c0 + cf*4);
            float4 o;
            o.x = elu(v.x + __ldg(&bias2[c0 + cf*4 + 0]));
            o.y = elu(v.y + __ldg(&bias2[c0 + cf*4 + 1]));
            o.z = elu(v.z + __ldg(&bias2[c0 + cf*4 + 2]));
            o.w = elu(v.w + __ldg(&bias2[c0 + cf*4 + 3]));
            *(float4*)(g_h2 + (size_t)(m0 + row)*C2v + c0 + cf*4) = o;
        }
    }
}

// ================= final dense (HBM streaming, float4) =============
__global__ void __launch_bounds__(256) dense_kernel(
    const float* __restrict__ Wm, const float* __restrict__ Ws)
{
    const int warp = threadIdx.x >> 5, lane = threadIdx.x & 31;
    const int l0 = blockIdx.x * 32 + warp * 4;
    const int ks = blockIdx.y;
    const int k0 = ks * KCHUNK;

    const float* Wp = (l0 < 256) ? (Wm + (size_t)l0 * KDv)
                                 : (Ws + (size_t)(l0 - 256) * KDv);
    const float* f = g_h3;

    float acc[4][8];
    #pragma unroll
    for (int j = 0; j < 4; j++)
        #pragma unroll
        for (int b = 0; b < 8; b++) acc[j][b] = 0.f;

    #pragma unroll 2
    for (int k = k0 + lane*4; k < k0 + KCHUNK; k += 128) {
        float4 fv[8];
        #pragma unroll
        for (int b = 0; b < 8; b++) fv[b] = *(const float4*)(f + (size_t)b*KDv + k);
        #pragma unroll
        for (int j = 0; j < 4; j++) {
            float4 wv = *(const float4*)(Wp + (size_t)j*KDv + k);
            #pragma unroll
            for (int b = 0; b < 8; b++) {
                acc[j][b] += wv.x * fv[b].x + wv.y * fv[b].y
                           + wv.z * fv[b].z + wv.w * fv[b].w;
            }
        }
    }

    #pragma unroll
    for (int j = 0; j < 4; j++)
        #pragma unroll
        for (int b = 0; b < 8; b++) {
            float v = acc[j][b];
            #pragma unroll
            for (int off = 16; off > 0; off >>= 1)
                v += __shfl_xor_sync(0xffffffffu, v, off);
            acc[j][b] = v;
        }

    if (lane == 0) {
        #pragma unroll
        for (int j = 0; j < 4; j++)
            #pragma unroll
            for (int b = 0; b < 8; b++)
                g_part[((size_t)ks*Bv + b)*LOUT + l0 + j] = acc[j][b];
    }
}

__global__ void reduce_kernel(const float* __restrict__ bm,
                              const float* __restrict__ bs,
                              float* __restrict__ out)
{
    int e = blockIdx.x * 256 + threadIdx.x;
    if (e >= Bv*LOUT) return;
    int b = e >> 9, l = e & 511;
    float acc = (l < 256) ? bm[l] : bs[l - 256];
    #pragma unroll 5
    for (int ks = 0; ks < KSPLIT; ks++)
        acc += g_part[((size_t)ks*Bv + b)*LOUT + l];
    out[e] = acc;
}

// ================= launch =========================================
extern "C" void kernel_launch(void* const* d_in, const int* in_sizes, int n_in,
                              void* d_out, int out_size)
{
    const float* x    = (const float*)d_in[0];
    const int*   nb0  = (const int*)  d_in[1];
    const int*   nb1  = (const int*)  d_in[2];
    const int*   nb2  = (const int*)  d_in[3];
    const int*   nb3  = (const int*)  d_in[4];
    const float* w0   = (const float*)d_in[5];
    const float* bia0 = (const float*)d_in[6];
    const float* ww0  = (const float*)d_in[7];
    const float* pn1  = (const float*)d_in[8];
    const float* w2   = (const float*)d_in[9];
    const float* bia2 = (const float*)d_in[10];
    const float* ww2  = (const float*)d_in[11];
    const float* pn3  = (const float*)d_in[12];
    const float* Wm   = (const float*)d_in[13];
    const float* bm   = (const float*)d_in[14];
    const float* Ws   = (const float*)d_in[15];
    const float* bs   = (const float*)d_in[16];
    float* out = (float*)d_out;

    cudaFuncSetAttribute(gemm_wmma_kernel,
                         cudaFuncAttributeMaxDynamicSharedMemorySize, GEMM_SMEM);

    conv0_kernel<<<P0v/CPTS, 512>>>(x, nb0, w0, bia0, ww0);
    pool_kernel<C1v, P0v, P1v, 0><<<P1v, C1v*Bv>>>(nb1, pn1);
    conv2s_kernel<<<P1v, 256>>>(nb2, ww2, w2);
    gemm_wmma_kernel<<<(NROW + 127)/128, 512, GEMM_SMEM>>>(bia2);
    pool_kernel<C2v, P1v, P2v, 1><<<P2v, C2v*Bv>>>(nb3, pn3);
    dense_kernel<<<dim3(16, KSPLIT), 256>>>(Wm, Ws);
    reduce_kernel<<<(Bv*LOUT + 255)/256, 256>>>(bm, bs, out);
}